// round 12
// baseline (speedup 1.0000x reference)
#include <cuda_runtime.h>
#include <math.h>
#include <stdint.h>

#define Bb   4
#define Nn   2048
#define FEAT 512
#define HIDD 512
#define Hh   8
#define HD   64
#define ROWS (Bb*Nn)          // 8192
#define BH   (Bb*Hh)          // 32

// ---------------- scratch (static device arrays; per-z doubled) ----------------
__device__ float g_qkv[(size_t)2*ROWS*3*HIDD];
__device__ float g_q[(size_t)2*ROWS*HIDD];    // [z][BH,N,HD], q pre-scaled by log2e/8
__device__ float g_k[(size_t)2*ROWS*HIDD];
__device__ float g_v[(size_t)2*ROWS*HIDD];
__device__ float g_o[(size_t)2*ROWS*HIDD];    // [z][B,N,HID]
__device__ float g_msg[(size_t)2*ROWS*HIDD];
__device__ float g_h[(size_t)2*ROWS*2*FEAT];
__device__ float g_g[(size_t)2*ROWS*2*FEAT];
// transposed weights [N][K]
__device__ float g_wqkvT[(size_t)(3*HIDD)*FEAT];
__device__ float g_wprojT[(size_t)HIDD*HIDD];
__device__ float g_w1T[(size_t)(2*FEAT)*(FEAT+HIDD)];
__device__ float g_w2T[(size_t)FEAT*(2*FEAT)];

// ---------------- helpers ----------------
__device__ __forceinline__ uint32_t s2u(const void* p) {
    return (uint32_t)__cvta_generic_to_shared(p);
}
__device__ __forceinline__ void cpa16(uint32_t dst, const void* src) {
    asm volatile("cp.async.cg.shared.global [%0], [%1], 16;\n" :: "r"(dst), "l"(src));
}
__device__ __forceinline__ void cpa_commit() {
    asm volatile("cp.async.commit_group;\n");
}
template<int N> __device__ __forceinline__ void cpa_wait() {
    asm volatile("cp.async.wait_group %0;\n" :: "n"(N));
}
__device__ __forceinline__ void ldsm_x4(uint32_t& r0, uint32_t& r1,
                                        uint32_t& r2, uint32_t& r3, uint32_t addr) {
    asm volatile("ldmatrix.sync.aligned.m8n8.x4.shared.b16 {%0,%1,%2,%3}, [%4];"
        : "=r"(r0), "=r"(r1), "=r"(r2), "=r"(r3) : "r"(addr));
}
__device__ __forceinline__ float ex2f(float x) {
    float r;
    asm("ex2.approx.f32 %0, %1;" : "=f"(r) : "f"(x));
    return r;
}

// mma on raw fp32 bits: tensor core truncates to tf32
__device__ __forceinline__ void mma_tf32(float* d,
    uint32_t a0, uint32_t a1, uint32_t a2, uint32_t a3,
    uint32_t b0, uint32_t b1)
{
    asm volatile(
        "mma.sync.aligned.m16n8k8.row.col.f32.tf32.tf32.f32 "
        "{%0,%1,%2,%3},{%4,%5,%6,%7},{%8,%9},{%0,%1,%2,%3};"
        : "+f"(d[0]), "+f"(d[1]), "+f"(d[2]), "+f"(d[3])
        : "r"(a0), "r"(a1), "r"(a2), "r"(a3), "r"(b0), "r"(b1));
}

// ---------------- merged weight transpose: all 4 matrices, flat tile grid ----------------
__global__ __launch_bounds__(256) void trw_kernel(
    const float* __restrict__ s0, float* __restrict__ d0p,
    const float* __restrict__ s1, float* __restrict__ d1p,
    const float* __restrict__ s2, float* __restrict__ d2p,
    const float* __restrict__ s3, float* __restrict__ d3p)
{
    __shared__ float tile[32][33];
    int tb = blockIdx.x;
    const float* src; float* dst; int R, C, lt;
    if (tb < 768)       { src=s0; dst=d0p; R=FEAT;      C=3*HIDD; lt=tb; }
    else if (tb < 1024) { src=s1; dst=d1p; R=HIDD;      C=HIDD;   lt=tb-768; }
    else if (tb < 2048) { src=s2; dst=d2p; R=FEAT+HIDD; C=2*FEAT; lt=tb-1024; }
    else                { src=s3; dst=d3p; R=2*FEAT;    C=FEAT;   lt=tb-2048; }
    int tC = C >> 5;
    int bx = lt % tC, by = lt / tC;

    int tx = threadIdx.x & 31, ty = threadIdx.x >> 5;
    int x = bx*32 + tx;
    #pragma unroll
    for (int i = ty; i < 32; i += 8) {
        int y = by*32 + i;
        tile[i][tx] = src[(size_t)y*C + x];
    }
    __syncthreads();
    int xt = by*32 + tx;
    #pragma unroll
    for (int i = ty; i < 32; i += 8) {
        int yt = bx*32 + i;
        dst[(size_t)yt*R + xt] = tile[tx][i];
    }
}

// ---------------- batched tf32 GEMM over z=0,1; 3-stage cp.async + LDSM, K-tile 32 ----------------
// 128x128 block tile, K-tile 32, 256 threads (8 warps, 4x2), warp tile 32x64.
// Stage: A [128][36] (4608 w) + B^T [128][36] (4608 w) = 9216 words.
#define GST_WORDS 9216
#define GSM_BYTES (3*GST_WORDS*4)   // 110592

__global__ __launch_bounds__(256, 2) void gemm_tf32(
    const float* __restrict__ A0, const float* __restrict__ A1, int lda,
    const float* __restrict__ A2_0, const float* __restrict__ A2_1, int lda2, int ksplit,
    const float* __restrict__ BT,
    const float* __restrict__ bias,
    const float* __restrict__ R0, const float* __restrict__ R1, int ldr,
    float* __restrict__ C, size_t zstrC, int ldc, int K)
{
    extern __shared__ uint32_t gsm[];

    const int z = blockIdx.z;
    const float* A     = z ? A1   : A0;
    const float* A2    = z ? A2_1 : A2_0;
    const float* resid = z ? R1   : R0;
    float* Cz = C + (size_t)z * zstrC;

    const int t    = threadIdx.x;
    const int lane = t & 31;
    const int warp = t >> 5;
    const int wm   = warp & 3;
    const int wn   = warp >> 2;
    const int rb   = blockIdx.y * 128;
    const int cb   = blockIdx.x * 128;

    const int arow = t >> 1;           // 0..127
    const int ah   = (t & 1) * 16;     // 0 or 16

    const int gid  = lane >> 2;
    const int tig  = lane & 3;

    const int a_r = ((lane >> 3) & 1)*8 + (lane & 7);
    const int a_c = (lane >> 4) * 4;
    const int b_r = (lane >> 4)*8 + (lane & 7);
    const int b_c = ((lane >> 3) & 1) * 4;

    const uint32_t smbase = s2u(gsm);

    auto issue_copy = [&](int kt, int s) {
        int kg = (kt << 5) + ah;
        const float* asrc = (A2 && kg >= ksplit)
            ? A2 + (size_t)(rb + arow) * lda2 + (kg - ksplit)
            : A  + (size_t)(rb + arow) * lda  + kg;
        uint32_t adst = smbase + (uint32_t)(s*GST_WORDS + arow*36 + ah) * 4;
        cpa16(adst,      asrc);
        cpa16(adst + 16, asrc + 4);
        cpa16(adst + 32, asrc + 8);
        cpa16(adst + 48, asrc + 12);
        const float* bsrc = BT + (size_t)(cb + arow) * K + kg;
        uint32_t bdst = smbase + (uint32_t)(s*GST_WORDS + 4608 + arow*36 + ah) * 4;
        cpa16(bdst,      bsrc);
        cpa16(bdst + 16, bsrc + 4);
        cpa16(bdst + 32, bsrc + 8);
        cpa16(bdst + 48, bsrc + 12);
        cpa_commit();
    };

    float acc[2][8][4] = {};

    const int nk = K >> 5;
    issue_copy(0, 0);
    if (nk > 1) issue_copy(1, 1);

    for (int kt = 0; kt < nk; ++kt) {
        const int s = kt % 3;
        if (kt < nk - 1) cpa_wait<1>(); else cpa_wait<0>();
        __syncthreads();
        if (kt + 2 < nk) issue_copy(kt + 2, (kt + 2) % 3);

        const uint32_t abase = smbase + (uint32_t)(s*GST_WORDS)*4;
        const uint32_t bbase = abase + 4608*4;
        #pragma unroll
        for (int ks = 0; ks < 4; ++ks) {
            uint32_t af0[4], af1[4];
            ldsm_x4(af0[0], af0[1], af0[2], af0[3],
                abase + (uint32_t)((wm*32 + a_r)*36 + ks*8 + a_c)*4);
            ldsm_x4(af1[0], af1[1], af1[2], af1[3],
                abase + (uint32_t)((wm*32 + 16 + a_r)*36 + ks*8 + a_c)*4);
            #pragma unroll
            for (int j = 0; j < 4; ++j) {
                uint32_t bf0, bf1, bf2, bf3;
                ldsm_x4(bf0, bf1, bf2, bf3,
                    bbase + (uint32_t)((wn*64 + j*16 + b_r)*36 + ks*8 + b_c)*4);
                mma_tf32(acc[0][2*j],   af0[0], af0[1], af0[2], af0[3], bf0, bf1);
                mma_tf32(acc[1][2*j],   af1[0], af1[1], af1[2], af1[3], bf0, bf1);
                mma_tf32(acc[0][2*j+1], af0[0], af0[1], af0[2], af0[3], bf2, bf3);
                mma_tf32(acc[1][2*j+1], af1[0], af1[1], af1[2], af1[3], bf2, bf3);
            }
        }
    }

    #pragma unroll
    for (int mt = 0; mt < 2; ++mt) {
        #pragma unroll
        for (int nt = 0; nt < 8; ++nt) {
            int row0 = rb + wm*32 + mt*16 + gid;
            int col  = cb + wn*64 + nt*8 + 2*tig;
            float2 bz = *(const float2*)(bias + col);
            float2 o0, o1;
            o0.x = acc[mt][nt][0] + bz.x;
            o0.y = acc[mt][nt][1] + bz.y;
            o1.x = acc[mt][nt][2] + bz.x;
            o1.y = acc[mt][nt][3] + bz.y;
            if (resid != nullptr) {
                float2 r0 = *(const float2*)(resid + (size_t)row0 * ldr + col);
                float2 r1 = *(const float2*)(resid + (size_t)(row0+8) * ldr + col);
                o0.x += r0.x; o0.y += r0.y;
                o1.x += r1.x; o1.y += r1.y;
            }
            *(float2*)(Cz + (size_t)row0 * ldc + col)     = o0;
            *(float2*)(Cz + (size_t)(row0+8) * ldc + col) = o1;
        }
    }
}

// ---------------- RoPE + split; q pre-scaled by log2e/8 (softmax uses exp2) ----------------
__global__ __launch_bounds__(256) void rope_kernel(
    const float* __restrict__ qkv, const float* __restrict__ enc0,
    const float* __restrict__ enc1,
    float* __restrict__ qb, float* __restrict__ kb, float* __restrict__ vb)
{
    const int z = blockIdx.y;
    const float* enc = z ? enc1 : enc0;
    const float* qz  = qkv + (size_t)z * ROWS * 3*HIDD;
    const size_t zo  = (size_t)z * ROWS * HIDD;

    int idx = blockIdx.x * blockDim.x + threadIdx.x;
    int p  = idx & (HD/2 - 1);
    int tmp = idx >> 5;
    int h  = tmp & (Hh - 1);
    tmp >>= 3;
    int n  = tmp & (Nn - 1);
    int b  = tmp >> 11;

    size_t row  = (size_t)b * Nn + n;
    size_t base = row * (3*HIDD) + h * (HD*3) + (2*p)*3;
    float q0 = qz[base+0], k0 = qz[base+1], v0 = qz[base+2];
    float q1 = qz[base+3], k1 = qz[base+4], v1 = qz[base+5];

    size_t eb = row * HD + 2*p;
    const size_t ESTR = (size_t)Bb * Nn * HD;
    float f00 = enc[eb],      f01 = enc[eb+1];
    float f10 = enc[ESTR+eb], f11 = enc[ESTR+eb+1];

    const float QS = 0.125f * 1.44269504088896340736f;   // log2(e)/8
    float qo0 = (q0*f00 - q1*f10) * QS;
    float qo1 = (q1*f01 + q0*f11) * QS;
    float ko0 = k0*f00 - k1*f10;
    float ko1 = k1*f01 + k0*f11;

    size_t ob = zo + (((size_t)b*Hh + h) * Nn + n) * HD + 2*p;
    qb[ob]   = qo0; qb[ob+1] = qo1;
    kb[ob]   = ko0; kb[ob+1] = ko1;
    vb[ob]   = v0;  vb[ob+1] = v1;
}

// ---------------- tf32 flash attention: K+V double-buffered, 1 wait + 1 barrier per tile ----------------
// smem words: QP[128][68] (Q staging -> P), K[2][64][68], V[2][64][72]
#define QPOFF 0
#define KOFF  (128*68)                 // 8704
#define KSTRIDE (64*68)                // 4352
#define VOFF  (KOFF + 2*KSTRIDE)       // 17408
#define VSTRIDE (64*72)                // 4608
#define FLASH_SMEM_U32 (VOFF + 2*VSTRIDE)  // 26624 words = 106496 B

__global__ __launch_bounds__(256, 2) void flash_tf32(
    const float* __restrict__ Q, const float* __restrict__ K,
    const float* __restrict__ V, float* __restrict__ O)
{
    extern __shared__ uint32_t smu[];
    float* Ps = (float*)(smu + QPOFF);

    const int z  = blockIdx.z;
    const int bh = blockIdx.y;
    const int b  = bh >> 3;
    const int h  = bh & 7;
    const size_t zo = (size_t)z * ROWS * HIDD;
    const float* Qg = Q + zo + (size_t)bh * Nn * HD;
    const float* Kg = K + zo + (size_t)bh * Nn * HD;
    const float* Vg = V + zo + (size_t)bh * Nn * HD;
    float* Og = O + zo;

    const int t    = threadIdx.x;
    const int lane = t & 31;
    const int warp = t >> 5;
    const int gid  = lane >> 2;
    const int tig  = lane & 3;
    const int q0r  = blockIdx.x * 128;

    const uint32_t qpa = s2u(smu + QPOFF);
    const uint32_t ksa = s2u(smu + KOFF);
    const uint32_t vsa = s2u(smu + VOFF);

    const int a_r = ((lane >> 3) & 1)*8 + (lane & 7);
    const int a_c = (lane >> 4) * 4;
    const int b_r = (lane >> 4)*8 + (lane & 7);
    const int b_c = ((lane >> 3) & 1) * 4;

    // stage K(j0) and V(j0) into buffer s as ONE commit group
    auto stage_tile = [&](int j0, int s) {
        #pragma unroll
        for (int i = 0; i < 4; ++i) {
            int idx = t + 256*i;
            int row = idx >> 4, dq = (idx & 15) << 2;
            cpa16(ksa + (uint32_t)(s*KSTRIDE + row*68 + dq)*4,
                  Kg + (size_t)(j0 + row)*HD + dq);
            cpa16(vsa + (uint32_t)(s*VSTRIDE + row*72 + dq)*4,
                  Vg + (size_t)(j0 + row)*HD + dq);
        }
        cpa_commit();
    };

    // prologue: stage Q (group 1), tile 0 (group 2)
    #pragma unroll
    for (int i = 0; i < 8; ++i) {
        int idx = t + 256*i;
        int row = idx >> 4, dq = (idx & 15) << 2;
        cpa16(qpa + (uint32_t)(row*68 + dq)*4, Qg + (size_t)(q0r + row)*HD + dq);
    }
    cpa_commit();
    stage_tile(0, 0);

    cpa_wait<1>();      // Q done (tile 0 may still fly)
    __syncthreads();

    // hoist Q fragments from QP (per-warp rows; P store later uses same rows)
    uint32_t qf[8][4];
    #pragma unroll
    for (int ks = 0; ks < 8; ++ks)
        ldsm_x4(qf[ks][0], qf[ks][1], qf[ks][2], qf[ks][3],
            qpa + (uint32_t)((warp*16 + a_r)*68 + ks*8 + a_c)*4);

    float accO[8][4] = {};
    float mrow[2] = {-1e30f, -1e30f};
    float lrow[2] = {0.f, 0.f};

    const int NT = Nn / 64;
    for (int it = 0; it < NT; ++it) {
        const int cur = it & 1;
        cpa_wait<0>();      // tile(it) data complete
        __syncthreads();    // all warps finished tile it-1; tile it visible

        // prefetch tile it+1 into the buffer tile it-1 used (proven consumed)
        if (it + 1 < NT) stage_tile((it+1)*64, 1-cur);

        // S = Q @ K^T
        const uint32_t kb_base = ksa + (uint32_t)(cur*KSTRIDE)*4;
        float s[8][4] = {};
        #pragma unroll
        for (int ks = 0; ks < 8; ++ks) {
            #pragma unroll
            for (int j = 0; j < 4; ++j) {
                uint32_t kf0, kf1, kf2, kf3;
                ldsm_x4(kf0, kf1, kf2, kf3,
                    kb_base + (uint32_t)((j*16 + b_r)*68 + ks*8 + b_c)*4);
                mma_tf32(s[2*j],   qf[ks][0], qf[ks][1], qf[ks][2], qf[ks][3], kf0, kf1);
                mma_tf32(s[2*j+1], qf[ks][0], qf[ks][1], qf[ks][2], qf[ks][3], kf2, kf3);
            }
        }

        // online softmax (log2 domain; q pre-scaled by log2e/8)
        #pragma unroll
        for (int g = 0; g < 2; ++g) {
            float tm = -1e30f;
            #pragma unroll
            for (int nt = 0; nt < 8; ++nt)
                tm = fmaxf(tm, fmaxf(s[nt][2*g], s[nt][2*g+1]));
            tm = fmaxf(tm, __shfl_xor_sync(0xffffffffu, tm, 1));
            tm = fmaxf(tm, __shfl_xor_sync(0xffffffffu, tm, 2));
            float mn = fmaxf(mrow[g], tm);
            float alpha = ex2f(mrow[g] - mn);
            mrow[g] = mn;
            float rs = 0.f;
            #pragma unroll
            for (int nt = 0; nt < 8; ++nt) {
                float p0 = ex2f(s[nt][2*g]   - mn);
                float p1 = ex2f(s[nt][2*g+1] - mn);
                s[nt][2*g] = p0; s[nt][2*g+1] = p1;
                rs += p0 + p1;
            }
            rs += __shfl_xor_sync(0xffffffffu, rs, 1);
            rs += __shfl_xor_sync(0xffffffffu, rs, 2);
            lrow[g] = lrow[g]*alpha + rs;
            #pragma unroll
            for (int nt = 0; nt < 8; ++nt) {
                accO[nt][2*g]   *= alpha;
                accO[nt][2*g+1] *= alpha;
            }
        }

        // store P (raw fp32) to this warp's rows of QP
        {
            int r0 = warp*16 + gid;
            #pragma unroll
            for (int nt = 0; nt < 8; ++nt) {
                int pc = nt*8 + 2*tig;
                *(float2*)&Ps[r0*68 + pc]     = make_float2(s[nt][0], s[nt][1]);
                *(float2*)&Ps[(r0+8)*68 + pc] = make_float2(s[nt][2], s[nt][3]);
            }
        }
        __syncwarp();

        // O += P @ V (P frags via ldsm; V scalar broadcast loads)
        const uint32_t* Vc = smu + VOFF + cur*VSTRIDE;
        #pragma unroll
        for (int ks = 0; ks < 8; ++ks) {
            uint32_t pf0, pf1, pf2, pf3;
            ldsm_x4(pf0, pf1, pf2, pf3,
                qpa + (uint32_t)((warp*16 + a_r)*68 + ks*8 + a_c)*4);
            #pragma unroll
            for (int nt = 0; nt < 8; ++nt) {
                int n = nt*8 + gid;
                int k = ks*8 + tig;
                uint32_t b0 = Vc[k*72 + n];
                uint32_t b1 = Vc[(k+4)*72 + n];
                mma_tf32(accO[nt], pf0, pf1, pf2, pf3, b0, b1);
            }
        }
    }

    #pragma unroll
    for (int g = 0; g < 2; ++g) {
        float inv = 1.0f / lrow[g];
        int n = q0r + warp*16 + gid + 8*g;
        #pragma unroll
        for (int nt = 0; nt < 8; ++nt) {
            int col = h*64 + nt*8 + 2*tig;
            float2 o;
            o.x = accO[nt][2*g]   * inv;
            o.y = accO[nt][2*g+1] * inv;
            *(float2*)&Og[((size_t)b * Nn + n) * HIDD + col] = o;
        }
    }
}

// ---------------- LayerNorm + exact GELU (batched over z) ----------------
__global__ __launch_bounds__(256) void ln_gelu_kernel(
    const float* __restrict__ H, const float* __restrict__ g,
    const float* __restrict__ bta, float* __restrict__ out)
{
    __shared__ float red[256];
    const size_t rowi = (size_t)blockIdx.y * ROWS + blockIdx.x;
    const float* p = H + rowi * (2*FEAT);
    int t = threadIdx.x;
    float4 v = ((const float4*)p)[t];

    float s = v.x + v.y + v.z + v.w;
    red[t] = s; __syncthreads();
    for (int ss = 128; ss > 0; ss >>= 1) {
        if (t < ss) red[t] += red[t+ss];
        __syncthreads();
    }
    float mu = red[0] * (1.0f / (2*FEAT));
    __syncthreads();

    float d0 = v.x - mu, d1 = v.y - mu, d2 = v.z - mu, d3 = v.w - mu;
    red[t] = d0*d0 + d1*d1 + d2*d2 + d3*d3; __syncthreads();
    for (int ss = 128; ss > 0; ss >>= 1) {
        if (t < ss) red[t] += red[t+ss];
        __syncthreads();
    }
    float var = red[0] * (1.0f / (2*FEAT));
    float rs = rsqrtf(var + 1e-5f);

    int c = t << 2;
    float4 gv = *(const float4*)(g + c);
    float4 bv = *(const float4*)(bta + c);
    float y0 = d0 * rs * gv.x + bv.x;
    float y1 = d1 * rs * gv.y + bv.y;
    float y2 = d2 * rs * gv.z + bv.z;
    float y3 = d3 * rs * gv.w + bv.w;

    const float IS2 = 0.70710678118654752f;
    float4 o;
    o.x = 0.5f * y0 * (1.0f + erff(y0 * IS2));
    o.y = 0.5f * y1 * (1.0f + erff(y1 * IS2));
    o.z = 0.5f * y2 * (1.0f + erff(y2 * IS2));
    o.w = 0.5f * y3 * (1.0f + erff(y3 * IS2));
    ((float4*)(out + rowi * (2*FEAT)))[t] = o;
}

extern "C" void kernel_launch(void* const* d_in, const int* in_sizes, int n_in,
                              void* d_out, int out_size)
{
    const float* x0    = (const float*)d_in[0];
    const float* x1    = (const float*)d_in[1];
    const float* enc0  = (const float*)d_in[2];
    const float* enc1  = (const float*)d_in[3];
    const float* Wqkv  = (const float*)d_in[4];
    const float* bqkv  = (const float*)d_in[5];
    const float* Wproj = (const float*)d_in[6];
    const float* bproj = (const float*)d_in[7];
    const float* W1    = (const float*)d_in[8];
    const float* b1    = (const float*)d_in[9];
    const float* ln_g  = (const float*)d_in[10];
    const float* ln_b  = (const float*)d_in[11];
    const float* W2    = (const float*)d_in[12];
    const float* b2    = (const float*)d_in[13];
    float* out = (float*)d_out;

    float *qkv, *q, *k, *v, *o, *msg, *hh, *gg;
    float *wqkvT, *wprojT, *w1T, *w2T;
    cudaGetSymbolAddress((void**)&qkv, g_qkv);
    cudaGetSymbolAddress((void**)&q,   g_q);
    cudaGetSymbolAddress((void**)&k,   g_k);
    cudaGetSymbolAddress((void**)&v,   g_v);
    cudaGetSymbolAddress((void**)&o,   g_o);
    cudaGetSymbolAddress((void**)&msg, g_msg);
    cudaGetSymbolAddress((void**)&hh,  g_h);
    cudaGetSymbolAddress((void**)&gg,  g_g);
    cudaGetSymbolAddress((void**)&wqkvT,  g_wqkvT);
    cudaGetSymbolAddress((void**)&wprojT, g_wprojT);
    cudaGetSymbolAddress((void**)&w1T,    g_w1T);
    cudaGetSymbolAddress((void**)&w2T,    g_w2T);

    cudaFuncSetAttribute(gemm_tf32,
        cudaFuncAttributeMaxDynamicSharedMemorySize, GSM_BYTES);
    cudaFuncSetAttribute(flash_tf32,
        cudaFuncAttributeMaxDynamicSharedMemorySize, FLASH_SMEM_U32*4);

    // transpose all 4 weight matrices in one launch
    trw_kernel<<<2560, 256>>>(Wqkv, wqkvT, Wproj, wprojT, W1, w1T, W2, w2T);

    const size_t ZQKV = (size_t)ROWS*3*HIDD;
    const size_t ZH   = (size_t)ROWS*HIDD;
    const size_t Z2F  = (size_t)ROWS*2*FEAT;

    // qkv = x @ Wqkv + bqkv
    gemm_tf32<<<dim3(3*HIDD/128, ROWS/128, 2), 256, GSM_BYTES>>>(
        x0, x1, FEAT, nullptr, nullptr, 0, 1<<30,
        wqkvT, bqkv, nullptr, nullptr, 0,
        qkv, ZQKV, 3*HIDD, FEAT);

    rope_kernel<<<dim3((Bb*Nn*Hh*(HD/2))/256, 2), 256>>>(qkv, enc0, enc1, q, k, v);

    flash_tf32<<<dim3(Nn/128, BH, 2), 256, FLASH_SMEM_U32*4>>>(q, k, v, o);

    // message = O @ Wproj + bproj
    gemm_tf32<<<dim3(HIDD/128, ROWS/128, 2), 256, GSM_BYTES>>>(
        o, o + ZH, HIDD, nullptr, nullptr, 0, 1<<30,
        wprojT, bproj, nullptr, nullptr, 0,
        msg, ZH, HIDD, HIDD);

    // h = concat(x, msg) @ W1 + b1
    gemm_tf32<<<dim3(2*FEAT/128, ROWS/128, 2), 256, GSM_BYTES>>>(
        x0, x1, FEAT, msg, msg + ZH, HIDD, FEAT,
        w1T, b1, nullptr, nullptr, 0,
        hh, Z2F, 2*FEAT, FEAT + HIDD);

    ln_gelu_kernel<<<dim3(ROWS, 2), 256>>>(hh, ln_g, ln_b, gg);

    // out = x + g @ W2 + b2
    gemm_tf32<<<dim3(FEAT/128, ROWS/128, 2), 256, GSM_BYTES>>>(
        gg, gg + Z2F, 2*FEAT, nullptr, nullptr, 0, 1<<30,
        w2T, b2, x0, x1, FEAT,
        out, (size_t)ROWS*FEAT, FEAT, 2*FEAT);
}

// round 13
// speedup vs baseline: 1.1343x; 1.1343x over previous
#include <cuda_runtime.h>
#include <math.h>
#include <stdint.h>

#define Bb   4
#define Nn   2048
#define FEAT 512
#define HIDD 512
#define Hh   8
#define HD   64
#define ROWS (Bb*Nn)          // 8192
#define BH   (Bb*Hh)          // 32

// ---------------- scratch (static device arrays; per-z doubled) ----------------
__device__ float g_q[(size_t)2*ROWS*HIDD];    // [z][BH,N,HD], q pre-scaled by log2e/8
__device__ float g_k[(size_t)2*ROWS*HIDD];
__device__ float g_v[(size_t)2*ROWS*HIDD];
__device__ float g_o[(size_t)2*ROWS*HIDD];    // [z][B,N,HID]
__device__ float g_msg[(size_t)2*ROWS*HIDD];
__device__ float g_h[(size_t)2*ROWS*2*FEAT];
__device__ float g_g[(size_t)2*ROWS*2*FEAT];
// transposed weights [N][K] (wqkvT rows are PERMUTED: j = (c%3)*512 + c/3)
__device__ float g_wqkvT[(size_t)(3*HIDD)*FEAT];
__device__ float g_wprojT[(size_t)HIDD*HIDD];
__device__ float g_w1T[(size_t)(2*FEAT)*(FEAT+HIDD)];
__device__ float g_w2T[(size_t)FEAT*(2*FEAT)];

// ---------------- helpers ----------------
__device__ __forceinline__ uint32_t s2u(const void* p) {
    return (uint32_t)__cvta_generic_to_shared(p);
}
__device__ __forceinline__ void cpa16(uint32_t dst, const void* src) {
    asm volatile("cp.async.cg.shared.global [%0], [%1], 16;\n" :: "r"(dst), "l"(src));
}
__device__ __forceinline__ void cpa_commit() {
    asm volatile("cp.async.commit_group;\n");
}
template<int N> __device__ __forceinline__ void cpa_wait() {
    asm volatile("cp.async.wait_group %0;\n" :: "n"(N));
}
__device__ __forceinline__ void ldsm_x4(uint32_t& r0, uint32_t& r1,
                                        uint32_t& r2, uint32_t& r3, uint32_t addr) {
    asm volatile("ldmatrix.sync.aligned.m8n8.x4.shared.b16 {%0,%1,%2,%3}, [%4];"
        : "=r"(r0), "=r"(r1), "=r"(r2), "=r"(r3) : "r"(addr));
}
__device__ __forceinline__ float ex2f(float x) {
    float r;
    asm("ex2.approx.f32 %0, %1;" : "=f"(r) : "f"(x));
    return r;
}

// mma on raw fp32 bits: tensor core truncates to tf32
__device__ __forceinline__ void mma_tf32(float* d,
    uint32_t a0, uint32_t a1, uint32_t a2, uint32_t a3,
    uint32_t b0, uint32_t b1)
{
    asm volatile(
        "mma.sync.aligned.m16n8k8.row.col.f32.tf32.tf32.f32 "
        "{%0,%1,%2,%3},{%4,%5,%6,%7},{%8,%9},{%0,%1,%2,%3};"
        : "+f"(d[0]), "+f"(d[1]), "+f"(d[2]), "+f"(d[3])
        : "r"(a0), "r"(a1), "r"(a2), "r"(a3), "r"(b0), "r"(b1));
}

// ---------------- merged weight transpose (qkv rows permuted) ----------------
// tiles: Wqkv 768 | Wproj 256 | W1 1024 | W2 512  => 2560
__global__ __launch_bounds__(256) void trw_kernel(
    const float* __restrict__ s0, float* __restrict__ d0p,
    const float* __restrict__ s1, float* __restrict__ d1p,
    const float* __restrict__ s2, float* __restrict__ d2p,
    const float* __restrict__ s3, float* __restrict__ d3p)
{
    __shared__ float tile[32][33];
    int tb = blockIdx.x;
    const float* src; float* dst; int R, C, lt, perm;
    if (tb < 768)       { src=s0; dst=d0p; R=FEAT;      C=3*HIDD; lt=tb;      perm=1; }
    else if (tb < 1024) { src=s1; dst=d1p; R=HIDD;      C=HIDD;   lt=tb-768;  perm=0; }
    else if (tb < 2048) { src=s2; dst=d2p; R=FEAT+HIDD; C=2*FEAT; lt=tb-1024; perm=0; }
    else                { src=s3; dst=d3p; R=2*FEAT;    C=FEAT;   lt=tb-2048; perm=0; }
    int tC = C >> 5;
    int bx = lt % tC, by = lt / tC;

    int tx = threadIdx.x & 31, ty = threadIdx.x >> 5;
    int x = bx*32 + tx;
    #pragma unroll
    for (int i = ty; i < 32; i += 8) {
        int y = by*32 + i;
        tile[i][tx] = src[(size_t)y*C + x];
    }
    __syncthreads();
    int xt = by*32 + tx;
    #pragma unroll
    for (int i = ty; i < 32; i += 8) {
        int c = bx*32 + i;                     // original output column
        int jrow = perm ? ((c % 3)*512 + c/3) : c;
        dst[(size_t)jrow*R + xt] = tile[tx][i];
    }
}

// ---------------- batched tf32 GEMM over z=0,1; 3-stage cp.async + LDSM (K-tile 16) ----------------
// Stage: A [128][20] (2560 w) + B^T [128][20] (2560 w) = 5120 words.
#define GST_WORDS 5120
#define GSM_BYTES (3*GST_WORDS*4)   // 61440

__global__ __launch_bounds__(256, 2) void gemm_tf32(
    const float* __restrict__ A0, const float* __restrict__ A1, int lda,
    const float* __restrict__ A2_0, const float* __restrict__ A2_1, int lda2, int ksplit,
    const float* __restrict__ BT,
    const float* __restrict__ bias,
    const float* __restrict__ R0, const float* __restrict__ R1, int ldr,
    float* __restrict__ C, size_t zstrC, int ldc, int K)
{
    extern __shared__ uint32_t gsm[];

    const int z = blockIdx.z;
    const float* A     = z ? A1   : A0;
    const float* A2    = z ? A2_1 : A2_0;
    const float* resid = z ? R1   : R0;
    float* Cz = C + (size_t)z * zstrC;

    const int t    = threadIdx.x;
    const int lane = t & 31;
    const int warp = t >> 5;
    const int wm   = warp & 3;
    const int wn   = warp >> 2;
    const int rb   = blockIdx.y * 128;
    const int cb   = blockIdx.x * 128;

    const int arow = t >> 1;
    const int ah   = (t & 1) * 8;

    const int gid  = lane >> 2;
    const int tig  = lane & 3;

    const int a_r = ((lane >> 3) & 1)*8 + (lane & 7);
    const int a_c = (lane >> 4) * 4;
    const int b_r = (lane >> 4)*8 + (lane & 7);
    const int b_c = ((lane >> 3) & 1) * 4;

    const uint32_t smbase = s2u(gsm);

    auto issue_copy = [&](int kt, int s) {
        int kg = (kt << 4) + ah;
        const float* asrc = (A2 && kg >= ksplit)
            ? A2 + (size_t)(rb + arow) * lda2 + (kg - ksplit)
            : A  + (size_t)(rb + arow) * lda  + kg;
        uint32_t adst = smbase + (uint32_t)(s*GST_WORDS + arow*20 + ah) * 4;
        cpa16(adst,      asrc);
        cpa16(adst + 16, asrc + 4);
        const float* bsrc = BT + (size_t)(cb + arow) * K + kg;
        uint32_t bdst = smbase + (uint32_t)(s*GST_WORDS + 2560 + arow*20 + ah) * 4;
        cpa16(bdst,      bsrc);
        cpa16(bdst + 16, bsrc + 4);
        cpa_commit();
    };

    float acc[2][8][4] = {};

    const int nk = K >> 4;
    issue_copy(0, 0);
    if (nk > 1) issue_copy(1, 1);

    for (int kt = 0; kt < nk; ++kt) {
        const int s = kt % 3;
        if (kt < nk - 1) cpa_wait<1>(); else cpa_wait<0>();
        __syncthreads();
        if (kt + 2 < nk) issue_copy(kt + 2, (kt + 2) % 3);

        const uint32_t abase = smbase + (uint32_t)(s*GST_WORDS)*4;
        const uint32_t bbase = abase + 2560*4;
        #pragma unroll
        for (int ks = 0; ks < 2; ++ks) {
            uint32_t af0[4], af1[4];
            ldsm_x4(af0[0], af0[1], af0[2], af0[3],
                abase + (uint32_t)((wm*32 + a_r)*20 + ks*8 + a_c)*4);
            ldsm_x4(af1[0], af1[1], af1[2], af1[3],
                abase + (uint32_t)((wm*32 + 16 + a_r)*20 + ks*8 + a_c)*4);
            #pragma unroll
            for (int j = 0; j < 4; ++j) {
                uint32_t bf0, bf1, bf2, bf3;
                ldsm_x4(bf0, bf1, bf2, bf3,
                    bbase + (uint32_t)((wn*64 + j*16 + b_r)*20 + ks*8 + b_c)*4);
                mma_tf32(acc[0][2*j],   af0[0], af0[1], af0[2], af0[3], bf0, bf1);
                mma_tf32(acc[1][2*j],   af1[0], af1[1], af1[2], af1[3], bf0, bf1);
                mma_tf32(acc[0][2*j+1], af0[0], af0[1], af0[2], af0[3], bf2, bf3);
                mma_tf32(acc[1][2*j+1], af1[0], af1[1], af1[2], af1[3], bf2, bf3);
            }
        }
    }

    #pragma unroll
    for (int mt = 0; mt < 2; ++mt) {
        #pragma unroll
        for (int nt = 0; nt < 8; ++nt) {
            int row0 = rb + wm*32 + mt*16 + gid;
            int col  = cb + wn*64 + nt*8 + 2*tig;
            float2 bz = *(const float2*)(bias + col);
            float2 o0, o1;
            o0.x = acc[mt][nt][0] + bz.x;
            o0.y = acc[mt][nt][1] + bz.y;
            o1.x = acc[mt][nt][2] + bz.x;
            o1.y = acc[mt][nt][3] + bz.y;
            if (resid != nullptr) {
                float2 r0 = *(const float2*)(resid + (size_t)row0 * ldr + col);
                float2 r1 = *(const float2*)(resid + (size_t)(row0+8) * ldr + col);
                o0.x += r0.x; o0.y += r0.y;
                o1.x += r1.x; o1.y += r1.y;
            }
            *(float2*)(Cz + (size_t)row0 * ldc + col)     = o0;
            *(float2*)(Cz + (size_t)(row0+8) * ldc + col) = o1;
        }
    }
}

// ---------------- qkv GEMM with fused RoPE epilogue ----------------
// BT = permuted wqkvT: output col j -> (sec=j/512, h=(j%512)/64, hd=j%64).
// Epilogue applies RoPE to q/k pairs (hd even, hd+1) and writes [z][BH,N,HD].
__global__ __launch_bounds__(256, 2) void gemm_qkv(
    const float* __restrict__ A0, const float* __restrict__ A1,
    const float* __restrict__ BT,
    const float* __restrict__ bias,
    const float* __restrict__ enc0, const float* __restrict__ enc1,
    float* __restrict__ qb, float* __restrict__ kb, float* __restrict__ vb)
{
    extern __shared__ uint32_t gsm[];

    const int z = blockIdx.z;
    const float* A   = z ? A1   : A0;
    const float* enc = z ? enc1 : enc0;
    const size_t zo  = (size_t)z * ROWS * HIDD;

    const int t    = threadIdx.x;
    const int lane = t & 31;
    const int warp = t >> 5;
    const int wm   = warp & 3;
    const int wn   = warp >> 2;
    const int rb   = blockIdx.y * 128;
    const int cb   = blockIdx.x * 128;

    const int arow = t >> 1;
    const int ah   = (t & 1) * 8;

    const int gid  = lane >> 2;
    const int tig  = lane & 3;

    const int a_r = ((lane >> 3) & 1)*8 + (lane & 7);
    const int a_c = (lane >> 4) * 4;
    const int b_r = (lane >> 4)*8 + (lane & 7);
    const int b_c = ((lane >> 3) & 1) * 4;

    const uint32_t smbase = s2u(gsm);
    const int K = FEAT;

    auto issue_copy = [&](int kt, int s) {
        int kg = (kt << 4) + ah;
        const float* asrc = A + (size_t)(rb + arow) * FEAT + kg;
        uint32_t adst = smbase + (uint32_t)(s*GST_WORDS + arow*20 + ah) * 4;
        cpa16(adst,      asrc);
        cpa16(adst + 16, asrc + 4);
        const float* bsrc = BT + (size_t)(cb + arow) * K + kg;
        uint32_t bdst = smbase + (uint32_t)(s*GST_WORDS + 2560 + arow*20 + ah) * 4;
        cpa16(bdst,      bsrc);
        cpa16(bdst + 16, bsrc + 4);
        cpa_commit();
    };

    float acc[2][8][4] = {};

    const int nk = K >> 4;   // 32
    issue_copy(0, 0);
    issue_copy(1, 1);

    for (int kt = 0; kt < nk; ++kt) {
        const int s = kt % 3;
        if (kt < nk - 1) cpa_wait<1>(); else cpa_wait<0>();
        __syncthreads();
        if (kt + 2 < nk) issue_copy(kt + 2, (kt + 2) % 3);

        const uint32_t abase = smbase + (uint32_t)(s*GST_WORDS)*4;
        const uint32_t bbase = abase + 2560*4;
        #pragma unroll
        for (int ks = 0; ks < 2; ++ks) {
            uint32_t af0[4], af1[4];
            ldsm_x4(af0[0], af0[1], af0[2], af0[3],
                abase + (uint32_t)((wm*32 + a_r)*20 + ks*8 + a_c)*4);
            ldsm_x4(af1[0], af1[1], af1[2], af1[3],
                abase + (uint32_t)((wm*32 + 16 + a_r)*20 + ks*8 + a_c)*4);
            #pragma unroll
            for (int j = 0; j < 4; ++j) {
                uint32_t bf0, bf1, bf2, bf3;
                ldsm_x4(bf0, bf1, bf2, bf3,
                    bbase + (uint32_t)((wn*64 + j*16 + b_r)*20 + ks*8 + b_c)*4);
                mma_tf32(acc[0][2*j],   af0[0], af0[1], af0[2], af0[3], bf0, bf1);
                mma_tf32(acc[1][2*j],   af1[0], af1[1], af1[2], af1[3], bf0, bf1);
                mma_tf32(acc[0][2*j+1], af0[0], af0[1], af0[2], af0[3], bf2, bf3);
                mma_tf32(acc[1][2*j+1], af1[0], af1[1], af1[2], af1[3], bf2, bf3);
            }
        }
    }

    // fused RoPE epilogue
    const int sec = cb >> 9;                       // CTA-uniform: 0=q,1=k,2=v
    const float QS = 0.125f * 1.44269504088896340736f;
    const size_t ESTR = (size_t)Bb * Nn * HD;
    float* dst = (sec == 0) ? qb : (sec == 1) ? kb : vb;

    #pragma unroll
    for (int mt = 0; mt < 2; ++mt) {
        #pragma unroll
        for (int nt = 0; nt < 8; ++nt) {
            int c    = cb + wn*64 + nt*8 + 2*tig;  // even
            int tcol = c & 511;
            int h    = tcol >> 6;
            int hd   = tcol & 63;
            float bz0 = bias[h*192 + hd*3 + sec];
            float bz1 = bias[h*192 + (hd+1)*3 + sec];
            #pragma unroll
            for (int rr = 0; rr < 2; ++rr) {
                int row = rb + wm*32 + mt*16 + gid + rr*8;
                float v0 = acc[mt][nt][2*rr]   + bz0;
                float v1 = acc[mt][nt][2*rr+1] + bz1;
                float o0, o1;
                if (sec == 2) {
                    o0 = v0; o1 = v1;
                } else {
                    size_t eb = (size_t)row * HD + hd;
                    float f00 = enc[eb], f01 = enc[eb+1];
                    float f10 = enc[ESTR+eb], f11 = enc[ESTR+eb+1];
                    o0 = v0*f00 - v1*f10;
                    o1 = v1*f01 + v0*f11;
                    if (sec == 0) { o0 *= QS; o1 *= QS; }
                }
                int bb = row >> 11, n = row & 2047;
                *(float2*)&dst[zo + ((size_t)(bb*Hh + h)*Nn + n)*HD + hd] =
                    make_float2(o0, o1);
            }
        }
    }
}

// ---------------- tf32 flash attention (R11: K double-buffered, split waits) ----------------
// smem words: QP[128][68] (Q staging -> P), K[2][64][68], V[64][72]
#define QPOFF 0
#define KOFF  (128*68)                 // 8704
#define KSTRIDE (64*68)                // 4352
#define VOFF  (KOFF + 2*KSTRIDE)       // 17408
#define FLASH_SMEM_U32 (VOFF + 64*72)  // 22016 words = 88064 B

__global__ __launch_bounds__(256, 2) void flash_tf32(
    const float* __restrict__ Q, const float* __restrict__ K,
    const float* __restrict__ V, float* __restrict__ O)
{
    extern __shared__ uint32_t smu[];
    float*    Ps = (float*)(smu + QPOFF);
    uint32_t* Vs = smu + VOFF;

    const int z  = blockIdx.z;
    const int bh = blockIdx.y;
    const int b  = bh >> 3;
    const int h  = bh & 7;
    const size_t zo = (size_t)z * ROWS * HIDD;
    const float* Qg = Q + zo + (size_t)bh * Nn * HD;
    const float* Kg = K + zo + (size_t)bh * Nn * HD;
    const float* Vg = V + zo + (size_t)bh * Nn * HD;
    float* Og = O + zo;

    const int t    = threadIdx.x;
    const int lane = t & 31;
    const int warp = t >> 5;
    const int gid  = lane >> 2;
    const int tig  = lane & 3;
    const int q0r  = blockIdx.x * 128;

    const uint32_t qpa = s2u(smu + QPOFF);
    const uint32_t ksa = s2u(smu + KOFF);
    const uint32_t vsa = s2u(Vs);

    const int a_r = ((lane >> 3) & 1)*8 + (lane & 7);
    const int a_c = (lane >> 4) * 4;
    const int b_r = (lane >> 4)*8 + (lane & 7);
    const int b_c = ((lane >> 3) & 1) * 4;

    auto stage_k = [&](int j0, int s) {
        #pragma unroll
        for (int i = 0; i < 4; ++i) {
            int idx = t + 256*i;
            int row = idx >> 4, dq = (idx & 15) << 2;
            cpa16(ksa + (uint32_t)(s*KSTRIDE + row*68 + dq)*4,
                  Kg + (size_t)(j0 + row)*HD + dq);
        }
        cpa_commit();
    };
    auto stage_v = [&](int j0) {
        #pragma unroll
        for (int i = 0; i < 4; ++i) {
            int idx = t + 256*i;
            int row = idx >> 4, dq = (idx & 15) << 2;
            cpa16(vsa + (uint32_t)(row*72 + dq)*4,
                  Vg + (size_t)(j0 + row)*HD + dq);
        }
        cpa_commit();
    };

    // prologue: stage Q (into QP), K(0), V(0)
    #pragma unroll
    for (int i = 0; i < 8; ++i) {
        int idx = t + 256*i;
        int row = idx >> 4, dq = (idx & 15) << 2;
        cpa16(qpa + (uint32_t)(row*68 + dq)*4, Qg + (size_t)(q0r + row)*HD + dq);
    }
    cpa_commit();
    stage_k(0, 0);
    stage_v(0);

    cpa_wait<2>();      // Q done
    __syncthreads();

    // hoist Q fragments from QP (before P overwrites it)
    uint32_t qf[8][4];
    #pragma unroll
    for (int ks = 0; ks < 8; ++ks)
        ldsm_x4(qf[ks][0], qf[ks][1], qf[ks][2], qf[ks][3],
            qpa + (uint32_t)((warp*16 + a_r)*68 + ks*8 + a_c)*4);

    float accO[8][4] = {};
    float mrow[2] = {-1e30f, -1e30f};
    float lrow[2] = {0.f, 0.f};

    const int NT = Nn / 64;
    for (int it = 0; it < NT; ++it) {
        const int cur = it & 1;
        cpa_wait<1>();      // K(it) done (V(it) may still be in flight)
        __syncthreads();    // K visible; all warps past prior tile

        // S = Q @ K^T
        const uint32_t kb_base = ksa + (uint32_t)(cur*KSTRIDE)*4;
        float s[8][4] = {};
        #pragma unroll
        for (int ks = 0; ks < 8; ++ks) {
            #pragma unroll
            for (int j = 0; j < 4; ++j) {
                uint32_t kf0, kf1, kf2, kf3;
                ldsm_x4(kf0, kf1, kf2, kf3,
                    kb_base + (uint32_t)((j*16 + b_r)*68 + ks*8 + b_c)*4);
                mma_tf32(s[2*j],   qf[ks][0], qf[ks][1], qf[ks][2], qf[ks][3], kf0, kf1);
                mma_tf32(s[2*j+1], qf[ks][0], qf[ks][1], qf[ks][2], qf[ks][3], kf2, kf3);
            }
        }

        // online softmax (log2 domain; q pre-scaled by log2e/8)
        #pragma unroll
        for (int g = 0; g < 2; ++g) {
            float tm = -1e30f;
            #pragma unroll
            for (int nt = 0; nt < 8; ++nt)
                tm = fmaxf(tm, fmaxf(s[nt][2*g], s[nt][2*g+1]));
            tm = fmaxf(tm, __shfl_xor_sync(0xffffffffu, tm, 1));
            tm = fmaxf(tm, __shfl_xor_sync(0xffffffffu, tm, 2));
            float mn = fmaxf(mrow[g], tm);
            float alpha = ex2f(mrow[g] - mn);
            mrow[g] = mn;
            float rs = 0.f;
            #pragma unroll
            for (int nt = 0; nt < 8; ++nt) {
                float p0 = ex2f(s[nt][2*g]   - mn);
                float p1 = ex2f(s[nt][2*g+1] - mn);
                s[nt][2*g] = p0; s[nt][2*g+1] = p1;
                rs += p0 + p1;
            }
            rs += __shfl_xor_sync(0xffffffffu, rs, 1);
            rs += __shfl_xor_sync(0xffffffffu, rs, 2);
            lrow[g] = lrow[g]*alpha + rs;
            #pragma unroll
            for (int nt = 0; nt < 8; ++nt) {
                accO[nt][2*g]   *= alpha;
                accO[nt][2*g+1] *= alpha;
            }
        }

        // store P (raw fp32) to this warp's rows of QP
        {
            int r0 = warp*16 + gid;
            #pragma unroll
            for (int nt = 0; nt < 8; ++nt) {
                int pc = nt*8 + 2*tig;
                *(float2*)&Ps[r0*68 + pc]     = make_float2(s[nt][0], s[nt][1]);
                *(float2*)&Ps[(r0+8)*68 + pc] = make_float2(s[nt][2], s[nt][3]);
            }
        }
        __syncwarp();

        cpa_wait<0>();      // V(it) done
        __syncthreads();    // V visible; all warps done with K[1-cur]

        // prefetch K(it+1) (overlaps PV)
        if (it + 1 < NT) stage_k((it+1)*64, 1-cur);

        // O += P @ V (P frags via ldsm from QP; V scalar broadcast loads)
        #pragma unroll
        for (int ks = 0; ks < 8; ++ks) {
            uint32_t pf0, pf1, pf2, pf3;
            ldsm_x4(pf0, pf1, pf2, pf3,
                qpa + (uint32_t)((warp*16 + a_r)*68 + ks*8 + a_c)*4);
            #pragma unroll
            for (int nt = 0; nt < 8; ++nt) {
                int n = nt*8 + gid;
                int k = ks*8 + tig;
                uint32_t b0 = Vs[k*72 + n];
                uint32_t b1 = Vs[(k+4)*72 + n];
                mma_tf32(accO[nt], pf0, pf1, pf2, pf3, b0, b1);
            }
        }
        __syncthreads();    // all PV reads of V done

        // prefetch V(it+1) (overlaps next QK + softmax)
        if (it + 1 < NT) stage_v((it+1)*64);
    }

    #pragma unroll
    for (int g = 0; g < 2; ++g) {
        float inv = 1.0f / lrow[g];
        int n = q0r + warp*16 + gid + 8*g;
        #pragma unroll
        for (int nt = 0; nt < 8; ++nt) {
            int col = h*64 + nt*8 + 2*tig;
            float2 o;
            o.x = accO[nt][2*g]   * inv;
            o.y = accO[nt][2*g+1] * inv;
            *(float2*)&Og[((size_t)b * Nn + n) * HIDD + col] = o;
        }
    }
}

// ---------------- LayerNorm + exact GELU (batched over z) ----------------
__global__ __launch_bounds__(256) void ln_gelu_kernel(
    const float* __restrict__ H, const float* __restrict__ g,
    const float* __restrict__ bta, float* __restrict__ out)
{
    __shared__ float red[256];
    const size_t rowi = (size_t)blockIdx.y * ROWS + blockIdx.x;
    const float* p = H + rowi * (2*FEAT);
    int t = threadIdx.x;
    float4 v = ((const float4*)p)[t];

    float s = v.x + v.y + v.z + v.w;
    red[t] = s; __syncthreads();
    for (int ss = 128; ss > 0; ss >>= 1) {
        if (t < ss) red[t] += red[t+ss];
        __syncthreads();
    }
    float mu = red[0] * (1.0f / (2*FEAT));
    __syncthreads();

    float d0 = v.x - mu, d1 = v.y - mu, d2 = v.z - mu, d3 = v.w - mu;
    red[t] = d0*d0 + d1*d1 + d2*d2 + d3*d3; __syncthreads();
    for (int ss = 128; ss > 0; ss >>= 1) {
        if (t < ss) red[t] += red[t+ss];
        __syncthreads();
    }
    float var = red[0] * (1.0f / (2*FEAT));
    float rs = rsqrtf(var + 1e-5f);

    int c = t << 2;
    float4 gv = *(const float4*)(g + c);
    float4 bv = *(const float4*)(bta + c);
    float y0 = d0 * rs * gv.x + bv.x;
    float y1 = d1 * rs * gv.y + bv.y;
    float y2 = d2 * rs * gv.z + bv.z;
    float y3 = d3 * rs * gv.w + bv.w;

    const float IS2 = 0.70710678118654752f;
    float4 o;
    o.x = 0.5f * y0 * (1.0f + erff(y0 * IS2));
    o.y = 0.5f * y1 * (1.0f + erff(y1 * IS2));
    o.z = 0.5f * y2 * (1.0f + erff(y2 * IS2));
    o.w = 0.5f * y3 * (1.0f + erff(y3 * IS2));
    ((float4*)(out + rowi * (2*FEAT)))[t] = o;
}

extern "C" void kernel_launch(void* const* d_in, const int* in_sizes, int n_in,
                              void* d_out, int out_size)
{
    const float* x0    = (const float*)d_in[0];
    const float* x1    = (const float*)d_in[1];
    const float* enc0  = (const float*)d_in[2];
    const float* enc1  = (const float*)d_in[3];
    const float* Wqkv  = (const float*)d_in[4];
    const float* bqkv  = (const float*)d_in[5];
    const float* Wproj = (const float*)d_in[6];
    const float* bproj = (const float*)d_in[7];
    const float* W1    = (const float*)d_in[8];
    const float* b1    = (const float*)d_in[9];
    const float* ln_g  = (const float*)d_in[10];
    const float* ln_b  = (const float*)d_in[11];
    const float* W2    = (const float*)d_in[12];
    const float* b2    = (const float*)d_in[13];
    float* out = (float*)d_out;

    float *q, *k, *v, *o, *msg, *hh, *gg;
    float *wqkvT, *wprojT, *w1T, *w2T;
    cudaGetSymbolAddress((void**)&q,   g_q);
    cudaGetSymbolAddress((void**)&k,   g_k);
    cudaGetSymbolAddress((void**)&v,   g_v);
    cudaGetSymbolAddress((void**)&o,   g_o);
    cudaGetSymbolAddress((void**)&msg, g_msg);
    cudaGetSymbolAddress((void**)&hh,  g_h);
    cudaGetSymbolAddress((void**)&gg,  g_g);
    cudaGetSymbolAddress((void**)&wqkvT,  g_wqkvT);
    cudaGetSymbolAddress((void**)&wprojT, g_wprojT);
    cudaGetSymbolAddress((void**)&w1T,    g_w1T);
    cudaGetSymbolAddress((void**)&w2T,    g_w2T);

    cudaFuncSetAttribute(gemm_tf32,
        cudaFuncAttributeMaxDynamicSharedMemorySize, GSM_BYTES);
    cudaFuncSetAttribute(gemm_qkv,
        cudaFuncAttributeMaxDynamicSharedMemorySize, GSM_BYTES);
    cudaFuncSetAttribute(flash_tf32,
        cudaFuncAttributeMaxDynamicSharedMemorySize, FLASH_SMEM_U32*4);

    // transpose all 4 weight matrices (qkv permuted) in one launch
    trw_kernel<<<2560, 256>>>(Wqkv, wqkvT, Wproj, wprojT, W1, w1T, W2, w2T);

    const size_t ZH   = (size_t)ROWS*HIDD;
    const size_t Z2F  = (size_t)ROWS*2*FEAT;

    // q/k/v = rope(x @ Wqkv + bqkv), fused epilogue
    gemm_qkv<<<dim3(3*HIDD/128, ROWS/128, 2), 256, GSM_BYTES>>>(
        x0, x1, wqkvT, bqkv, enc0, enc1, q, k, v);

    flash_tf32<<<dim3(Nn/128, BH, 2), 256, FLASH_SMEM_U32*4>>>(q, k, v, o);

    // message = O @ Wproj + bproj
    gemm_tf32<<<dim3(HIDD/128, ROWS/128, 2), 256, GSM_BYTES>>>(
        o, o + ZH, HIDD, nullptr, nullptr, 0, 1<<30,
        wprojT, bproj, nullptr, nullptr, 0,
        msg, ZH, HIDD, HIDD);

    // h = concat(x, msg) @ W1 + b1
    gemm_tf32<<<dim3(2*FEAT/128, ROWS/128, 2), 256, GSM_BYTES>>>(
        x0, x1, FEAT, msg, msg + ZH, HIDD, FEAT,
        w1T, b1, nullptr, nullptr, 0,
        hh, Z2F, 2*FEAT, FEAT + HIDD);

    ln_gelu_kernel<<<dim3(ROWS, 2), 256>>>(hh, ln_g, ln_b, gg);

    // out = x + g @ W2 + b2
    gemm_tf32<<<dim3(FEAT/128, ROWS/128, 2), 256, GSM_BYTES>>>(
        gg, gg + Z2F, 2*FEAT, nullptr, nullptr, 0, 1<<30,
        w2T, b2, x0, x1, FEAT,
        out, (size_t)ROWS*FEAT, FEAT, 2*FEAT);
}